// round 1
// baseline (speedup 1.0000x reference)
#include <cuda_runtime.h>
#include <cuda_bf16.h>
#include <cstdint>

// Problem constants (fixed by the dataset)
#define NN   8192            // nodes
#define EE   262144          // edges
#define D0   128             // input dim
#define HD   256             // hidden dim

// ---------------- device scratch (no allocation allowed) ----------------
__device__ float g_agg[NN * HD];     // aggregation output (layer input to GEMM)
__device__ float g_h[NN * HD];       // GEMM output (hidden activations)
__device__ float g_dinv[NN];
__device__ int   g_cnt[NN];
__device__ int   g_off[NN + 1];
__device__ int   g_cur[NN];
__device__ int   g_col[EE];
__device__ float g_a[NN];
__device__ float g_b[NN];
__device__ float g_u[HD];
__device__ float g_v[HD];
__device__ float g_consts[2];
__device__ int   g_is64;

// ---------------- edge index access (int32 vs int64 detected at runtime) ---
__global__ void detect_kernel(const void* ei) {
    // int64 values in [0,8192) => every odd 4-byte word is 0. For int32 random
    // values in [0,8192) the chance all 32 odd words are 0 is ~(1/8192)^32 ~ 0.
    const int* w = (const int*)ei;
    int is64 = 1;
    for (int i = 0; i < 32; i++) {
        if (w[2 * i + 1] != 0) { is64 = 0; break; }
    }
    g_is64 = is64;
}

__device__ __forceinline__ int edge_at(const void* ei, int idx) {
    if (g_is64) return (int)((const long long*)ei)[idx];
    return ((const int*)ei)[idx];
}

// ---------------- CSR build -------------------------------------------------
__global__ void init_cnt_kernel() {
    int i = blockIdx.x * blockDim.x + threadIdx.x;
    if (i < NN) g_cnt[i] = 0;
}

__global__ void count_kernel(const void* ei) {
    int e = blockIdx.x * blockDim.x + threadIdx.x;
    if (e >= EE) return;
    int d = edge_at(ei, EE + e);   // dst row
    atomicAdd(&g_cnt[d], 1);
}

__global__ void dinv_kernel() {
    int i = blockIdx.x * blockDim.x + threadIdx.x;
    if (i < NN) g_dinv[i] = rsqrtf((float)(g_cnt[i] + 1));  // +1 self loop
}

// one block, 1024 threads; 8 counts per thread + Hillis-Steele over partials
__global__ void scan_kernel() {
    __shared__ int s[1024];
    int tid = threadIdx.x;
    int base = tid * 8;
    int c[8];
    int local = 0;
#pragma unroll
    for (int j = 0; j < 8; j++) { c[j] = g_cnt[base + j]; local += c[j]; }
    s[tid] = local;
    __syncthreads();
    for (int o = 1; o < 1024; o <<= 1) {
        int v = (tid >= o) ? s[tid - o] : 0;
        __syncthreads();
        s[tid] += v;
        __syncthreads();
    }
    int run = s[tid] - local;   // exclusive prefix of this thread's chunk
#pragma unroll
    for (int j = 0; j < 8; j++) {
        g_off[base + j] = run;
        g_cur[base + j] = run;
        run += c[j];
    }
    if (tid == 1023) g_off[NN] = run;
}

__global__ void fill_kernel(const void* ei) {
    int e = blockIdx.x * blockDim.x + threadIdx.x;
    if (e >= EE) return;
    int srow = edge_at(ei, e);
    int d    = edge_at(ei, EE + e);
    int pos = atomicAdd(&g_cur[d], 1);
    g_col[pos] = srow;
}

// ---------------- aggregation: out = D^-1/2 (A+I) D^-1/2 in ---------------
// One row handled by H/4 threads, each owning one float4 of the feature dim.
template <int H>
__global__ void agg_kernel(const float* __restrict__ in_opt) {
    constexpr int TPR = H / 4;        // threads per row
    constexpr int RPB = 256 / TPR;    // rows per block
    const float* in = in_opt ? in_opt : g_h;
    int lane = threadIdx.x % TPR;
    int row  = blockIdx.x * RPB + threadIdx.x / TPR;
    const float4* in4 = (const float4*)in;
    float di = g_dinv[row];
    float4 sv = in4[row * TPR + lane];
    float4 acc = make_float4(di * sv.x, di * sv.y, di * sv.z, di * sv.w);
    int e0 = g_off[row], e1 = g_off[row + 1];
    for (int e = e0; e < e1; e++) {
        int s = g_col[e];
        float w = g_dinv[s];
        float4 xv = in4[s * TPR + lane];
        acc.x += w * xv.x; acc.y += w * xv.y;
        acc.z += w * xv.z; acc.w += w * xv.w;
    }
    acc.x *= di; acc.y *= di; acc.z *= di; acc.w *= di;
    ((float4*)g_agg)[row * TPR + lane] = acc;
}

// ---------------- fp32 GEMM: C = relu(A @ W^T + b) -------------------------
// A [M,K] row-major (g_agg), W [Ncol,K] row-major, C [M,Ncol] (g_h).
// BM=BN=64, BK=16, 256 threads, 4x4 register tile.
__global__ __launch_bounds__(256) void gemm_kernel(
    const float* __restrict__ W, const float* __restrict__ bias,
    int K, int Ncol, int relu)
{
    __shared__ float As[16][64];
    __shared__ float Ws[16][64];
    const float* A = g_agg;
    float* C = g_h;
    int bx = blockIdx.x;              // col block (Ncol/64)
    int by = blockIdx.y;              // row block (M/64)
    int tid = threadIdx.x;
    int tx = tid & 15, ty = tid >> 4;
    int lrow = tid >> 2;              // 0..63
    int lk4  = (tid & 3) << 2;        // 0,4,8,12

    float acc[4][4] = {};
    const float* Arow = A + (size_t)(by * 64 + lrow) * K;
    const float* Wrow = W + (size_t)(bx * 64 + lrow) * K;

    for (int kc = 0; kc < K; kc += 16) {
        float4 av = *(const float4*)(Arow + kc + lk4);
        float4 wv = *(const float4*)(Wrow + kc + lk4);
        As[lk4 + 0][lrow] = av.x; As[lk4 + 1][lrow] = av.y;
        As[lk4 + 2][lrow] = av.z; As[lk4 + 3][lrow] = av.w;
        Ws[lk4 + 0][lrow] = wv.x; Ws[lk4 + 1][lrow] = wv.y;
        Ws[lk4 + 2][lrow] = wv.z; Ws[lk4 + 3][lrow] = wv.w;
        __syncthreads();
#pragma unroll
        for (int k = 0; k < 16; k++) {
            float4 a4 = *(const float4*)&As[k][ty * 4];
            float4 b4 = *(const float4*)&Ws[k][tx * 4];
            float ar[4] = {a4.x, a4.y, a4.z, a4.w};
            float br[4] = {b4.x, b4.y, b4.z, b4.w};
#pragma unroll
            for (int i = 0; i < 4; i++)
#pragma unroll
                for (int j = 0; j < 4; j++)
                    acc[i][j] = fmaf(ar[i], br[j], acc[i][j]);
        }
        __syncthreads();
    }
    float4 bv = *(const float4*)&bias[bx * 64 + tx * 4];
    float bb[4] = {bv.x, bv.y, bv.z, bv.w};
#pragma unroll
    for (int i = 0; i < 4; i++) {
        int m = by * 64 + ty * 4 + i;
        float o0 = acc[i][0] + bb[0];
        float o1 = acc[i][1] + bb[1];
        float o2 = acc[i][2] + bb[2];
        float o3 = acc[i][3] + bb[3];
        if (relu) {
            o0 = fmaxf(o0, 0.f); o1 = fmaxf(o1, 0.f);
            o2 = fmaxf(o2, 0.f); o3 = fmaxf(o3, 0.f);
        }
        *(float4*)&C[(size_t)m * Ncol + bx * 64 + tx * 4] =
            make_float4(o0, o1, o2, o3);
    }
}

// ---------------- u = out_W^T wi, v = out_W^T wj, constants ----------------
__global__ void uv_kernel(const float* __restrict__ outW,
                          const float* __restrict__ outb,
                          const float* __restrict__ edgeW,
                          const float* __restrict__ edgeb) {
    int k = threadIdx.x;  // 256
    float su = 0.f, sv = 0.f;
    for (int j = 0; j < HD; j++) {
        float w = outW[j * HD + k];
        su += w * edgeW[j];
        sv += w * edgeW[HD + j];
    }
    g_u[k] = su;
    g_v[k] = sv;
    if (k == 0) {
        float ca = edgeb[0], cb = 0.f;
        for (int j = 0; j < HD; j++) {
            ca += outb[j] * edgeW[j];
            cb += outb[j] * edgeW[HD + j];
        }
        g_consts[0] = ca;
        g_consts[1] = cb;
    }
}

// ---------------- a[i] = h_i . u + ca ; b[i] = h_i . v + cb ----------------
__global__ void ab_kernel() {
    int warp = threadIdx.x >> 5, lane = threadIdx.x & 31;
    int node = blockIdx.x * 8 + warp;
    const float4* h4 = (const float4*)(g_h + (size_t)node * HD);
    const float4* u4 = (const float4*)g_u;
    const float4* v4 = (const float4*)g_v;
    float su = 0.f, sv = 0.f;
#pragma unroll
    for (int t = 0; t < 2; t++) {
        int idx = lane + t * 32;
        float4 hv = h4[idx];
        float4 uu = u4[idx];
        float4 vv = v4[idx];
        su += hv.x * uu.x + hv.y * uu.y + hv.z * uu.z + hv.w * uu.w;
        sv += hv.x * vv.x + hv.y * vv.y + hv.z * vv.z + hv.w * vv.w;
    }
#pragma unroll
    for (int o = 16; o > 0; o >>= 1) {
        su += __shfl_down_sync(0xffffffffu, su, o);
        sv += __shfl_down_sync(0xffffffffu, sv, o);
    }
    if (lane == 0) {
        g_a[node] = su + g_consts[0];
        g_b[node] = sv + g_consts[1];
    }
}

// ---------------- logits[i,j] = a[i] + b[j] (268 MB store) -----------------
__global__ __launch_bounds__(256) void outer_kernel(float* __restrict__ out) {
    int i = blockIdx.x;
    float ai = g_a[i];
    float4* o = (float4*)(out + (size_t)i * NN);
    const float4* b4 = (const float4*)g_b;
#pragma unroll
    for (int t = 0; t < 8; t++) {
        int j = threadIdx.x + t * 256;
        float4 bv = __ldg(&b4[j]);
        float4 r = make_float4(ai + bv.x, ai + bv.y, ai + bv.z, ai + bv.w);
        __stcs(&o[j], r);   // streaming store: don't thrash L2
    }
}

// ---------------- launch ----------------------------------------------------
extern "C" void kernel_launch(void* const* d_in, const int* in_sizes, int n_in,
                              void* d_out, int out_size) {
    const float* x     = (const float*)d_in[0];
    const void*  ei    = d_in[1];
    const float* W0    = (const float*)d_in[2];
    const float* b0    = (const float*)d_in[3];
    const float* W1    = (const float*)d_in[4];
    const float* b1    = (const float*)d_in[5];
    const float* W2    = (const float*)d_in[6];
    const float* b2    = (const float*)d_in[7];
    const float* outW  = (const float*)d_in[8];
    const float* outb  = (const float*)d_in[9];
    const float* edgeW = (const float*)d_in[10];
    const float* edgeb = (const float*)d_in[11];
    float* out = (float*)d_out;

    // CSR build (replayed every call; deterministic up to fp sum order)
    detect_kernel<<<1, 1>>>(ei);
    init_cnt_kernel<<<NN / 256, 256>>>();
    count_kernel<<<EE / 256, 256>>>(ei);
    dinv_kernel<<<NN / 256, 256>>>();
    scan_kernel<<<1, 1024>>>();
    fill_kernel<<<EE / 256, 256>>>(ei);

    dim3 ggrid(HD / 64, NN / 64);

    // layer 0: aggregate x (128-d), then GEMM K=128 -> 256, relu
    agg_kernel<D0><<<NN / (256 / (D0 / 4)), 256>>>(x);
    gemm_kernel<<<ggrid, 256>>>(W0, b0, D0, HD, 1);

    // layer 1
    agg_kernel<HD><<<NN / (256 / (HD / 4)), 256>>>(nullptr);
    gemm_kernel<<<ggrid, 256>>>(W1, b1, HD, HD, 1);

    // layer 2
    agg_kernel<HD><<<NN / (256 / (HD / 4)), 256>>>(nullptr);
    gemm_kernel<<<ggrid, 256>>>(W2, b2, HD, HD, 1);

    // fold out_W / edge_W into two 256-vectors + constants
    uv_kernel<<<1, HD>>>(outW, outb, edgeW, edgeb);
    ab_kernel<<<NN / 8, 256>>>();

    // final 8192x8192 broadcast-sum
    outer_kernel<<<NN, 256>>>(out);
}